// round 5
// baseline (speedup 1.0000x reference)
#include <cuda_runtime.h>

// B=16, Wn=64, K=256, E=128, O=64

typedef unsigned long long ull;

__device__ __forceinline__ ull f2_add(ull a, ull b) {
    ull r; asm("add.rn.f32x2 %0,%1,%2;" : "=l"(r) : "l"(a), "l"(b)); return r;
}
__device__ __forceinline__ ull f2_fma(ull a, ull b, ull c) {
    ull r; asm("fma.rn.f32x2 %0,%1,%2,%3;" : "=l"(r) : "l"(a), "l"(b), "l"(c)); return r;
}
__device__ __forceinline__ float f2_hadd(ull a) {
    float lo, hi; asm("mov.b64 {%0,%1},%2;" : "=f"(lo), "=f"(hi) : "l"(a)); return lo + hi;
}
__device__ __forceinline__ ull f2_dup(float v) {
    ull r; asm("mov.b64 %0,{%1,%1};" : "=l"(r) : "f"(v)); return r;
}
__device__ __forceinline__ void f2_unpack(ull a, float& lo, float& hi) {
    asm("mov.b64 {%0,%1},%2;" : "=f"(lo), "=f"(hi) : "l"(a));
}

// Scratch
__device__ float g_L[16 * 256 * 128];
__device__ float g_R[16 * 256 * 128];
__device__ float g_sL[16 * 256];
__device__ float g_sR[16 * 256];
__device__ float g_h[16 * 256 * 64];

// ---------------------------------------------------------------------------
// k1: C[4096,256] = A[4096,64] x W[256,64]^T ; 8m x 4n register tiles
// grid = 256 blocks, 128 threads
// ---------------------------------------------------------------------------
__global__ void __launch_bounds__(128, 4)
k1_lr(const float* __restrict__ x, const float* __restrict__ lin_w,
      const float* __restrict__ lin_b) {
    __shared__ float As[64 * 68];
    __shared__ float Ws[64 * 68];

    int bx = blockIdx.x;
    int mt = bx >> 2, nt = bx & 3;
    int b = mt >> 2, k0 = (mt & 3) * 64;
    int half = nt >> 1, e0 = (nt & 1) * 64;
    int tid = threadIdx.x;

#pragma unroll
    for (int t = 0; t < 8; t++) {
        int idx = t * 128 + tid;
        int w = idx >> 4, m4 = idx & 15;
        float4 v = *reinterpret_cast<const float4*>(x + b * 16384 + w * 256 + k0 + m4 * 4);
        *reinterpret_cast<float4*>(&As[w * 68 + m4 * 4]) = v;
    }
#pragma unroll
    for (int t = 0; t < 8; t++) {
        int idx = t * 128 + tid;
        int n = idx >> 4, w4 = idx & 15;
        float4 v = *reinterpret_cast<const float4*>(lin_w + (e0 + n) * 128 + half * 64 + w4 * 4);
        Ws[(w4 * 4 + 0) * 68 + n] = v.x;
        Ws[(w4 * 4 + 1) * 68 + n] = v.y;
        Ws[(w4 * 4 + 2) * 68 + n] = v.z;
        Ws[(w4 * 4 + 3) * 68 + n] = v.w;
    }
    __syncthreads();

    int mg = tid >> 4, ng = tid & 15;
    ull acc[4][4];
#pragma unroll
    for (int n = 0; n < 4; n++)
#pragma unroll
        for (int p = 0; p < 4; p++) acc[n][p] = 0ULL;

#pragma unroll 8
    for (int w = 0; w < 64; w++) {
        const ull* ap = reinterpret_cast<const ull*>(&As[w * 68 + mg * 8]);
        ull a0 = ap[0], a1 = ap[1], a2 = ap[2], a3 = ap[3];
        float4 wn = *reinterpret_cast<const float4*>(&Ws[w * 68 + ng * 4]);
        ull w0 = f2_dup(wn.x), w1 = f2_dup(wn.y), w2 = f2_dup(wn.z), w3 = f2_dup(wn.w);
        acc[0][0] = f2_fma(a0, w0, acc[0][0]); acc[0][1] = f2_fma(a1, w0, acc[0][1]);
        acc[0][2] = f2_fma(a2, w0, acc[0][2]); acc[0][3] = f2_fma(a3, w0, acc[0][3]);
        acc[1][0] = f2_fma(a0, w1, acc[1][0]); acc[1][1] = f2_fma(a1, w1, acc[1][1]);
        acc[1][2] = f2_fma(a2, w1, acc[1][2]); acc[1][3] = f2_fma(a3, w1, acc[1][3]);
        acc[2][0] = f2_fma(a0, w2, acc[2][0]); acc[2][1] = f2_fma(a1, w2, acc[2][1]);
        acc[2][2] = f2_fma(a2, w2, acc[2][2]); acc[2][3] = f2_fma(a3, w2, acc[2][3]);
        acc[3][0] = f2_fma(a0, w3, acc[3][0]); acc[3][1] = f2_fma(a1, w3, acc[3][1]);
        acc[3][2] = f2_fma(a2, w3, acc[3][2]); acc[3][3] = f2_fma(a3, w3, acc[3][3]);
    }

    float4 lb4 = make_float4(0.f, 0.f, 0.f, 0.f);
    if (half == 0) lb4 = *reinterpret_cast<const float4*>(lin_b + e0 + ng * 4);
    float* outbase = (half ? g_R : g_L) + (b * 256 + k0 + mg * 8) * 128 + e0 + ng * 4;
#pragma unroll
    for (int p = 0; p < 4; p++) {
        float lo[4], hi[4];
#pragma unroll
        for (int n = 0; n < 4; n++) f2_unpack(acc[n][p], lo[n], hi[n]);
        *reinterpret_cast<float4*>(outbase + (2 * p) * 128) =
            make_float4(lo[0] + lb4.x, lo[1] + lb4.y, lo[2] + lb4.z, lo[3] + lb4.w);
        *reinterpret_cast<float4*>(outbase + (2 * p + 1) * 128) =
            make_float4(hi[0] + lb4.x, hi[1] + lb4.y, hi[2] + lb4.z, hi[3] + lb4.w);
    }
}

// ---------------------------------------------------------------------------
// k1b: sL/sR row dots. grid = 256 x 128 thr (8 thr per row)
// ---------------------------------------------------------------------------
__global__ void __launch_bounds__(128, 8)
k1b_s(const float* __restrict__ a) {
    __shared__ float as[128];
    int tid = threadIdx.x;
    as[tid] = a[tid];
    __syncthreads();

    int row = blockIdx.x * 16 + (tid >> 3);
    int g = tid & 7;
    const float4* Lp = reinterpret_cast<const float4*>(g_L + row * 128 + g * 16);
    const float4* Rp = reinterpret_cast<const float4*>(g_R + row * 128 + g * 16);
    const float4* Ap = reinterpret_cast<const float4*>(as) + g * 4;
    float sl = 0.f, sr = 0.f;
#pragma unroll
    for (int u = 0; u < 4; u++) {
        float4 lv = Lp[u], rv = Rp[u], av = Ap[u];
        sl += lv.x * av.x + lv.y * av.y + lv.z * av.z + lv.w * av.w;
        sr += rv.x * av.x + rv.y * av.y + rv.z * av.z + rv.w * av.w;
    }
#pragma unroll
    for (int o = 4; o > 0; o >>= 1) {
        sl += __shfl_down_sync(0xffffffffu, sl, o, 8);
        sr += __shfl_down_sync(0xffffffffu, sr, o, 8);
    }
    if (g == 0) {
        g_sL[row] = 0.6f * sl;
        g_sR[row] = 0.6f * sr;
    }
}

// ---------------------------------------------------------------------------
// k2: e-scores + softmax + h.  grid = 256 (16b x 16 itiles of 16), 256 thr.
// e-phase: 256 threads = 4 ig x 16 jg x 4 e-quarters; 4i x 4j register tiles.
// smem 109,952 B -> 2 blocks/SM.
// ---------------------------------------------------------------------------
__global__ void __launch_bounds__(256, 2)
k2_attn(const float* __restrict__ x, const float* __restrict__ bias_kk,
        const float* __restrict__ a) {
    extern __shared__ float S[];
    const int LS = 0;        // 16 x 132
    const int RS = 2112;     // 64 x 130   (reused as h partials 2 x 16 x 64)
    const int ES = 10432;    // 4 x (16 x 260) e-quarter partials; then probs in q0
    const int CS = 27072;    // 128
    const int SRS = 27200;   // 256
    const int SLS = 27456;   // 16
    const int INVS = 27472;  // 16        (total 27488 floats = 109,952 B)
    const ull ABSM = 0x7FFFFFFF7FFFFFFFULL;

    int tid = threadIdx.x;
    int b = blockIdx.x >> 4;
    int i0 = (blockIdx.x & 15) << 4;

    const float* Lg = g_L + (b * 256 + i0) * 128;
#pragma unroll
    for (int t = 0; t < 2; t++) {
        int idx = t * 256 + tid;          // 512 float4
        int row = idx >> 5, c4 = idx & 31;
        float4 v = *reinterpret_cast<const float4*>(Lg + row * 128 + c4 * 4);
        *reinterpret_cast<float4*>(&S[LS + row * 132 + c4 * 4]) = v;
    }
    if (tid < 128) S[CS + tid] = 0.4f * a[tid];
    S[SRS + tid] = g_sR[b * 256 + tid];
    if (tid < 16) S[SLS + tid] = g_sL[b * 256 + i0 + tid];

    int eh = tid >> 6;          // e-quarter 0..3
    int r = tid & 63;
    int ig = r >> 4;            // 0..3 -> i = ig + 4u
    int jg = r & 15;            // 0..15 -> j = jt*64 + jg + 16v
    const ull* Lp0 = reinterpret_cast<const ull*>(&S[LS + (ig) * 132]) + eh * 16;
    const ull* Lp1 = reinterpret_cast<const ull*>(&S[LS + (ig + 4) * 132]) + eh * 16;
    const ull* Lp2 = reinterpret_cast<const ull*>(&S[LS + (ig + 8) * 132]) + eh * 16;
    const ull* Lp3 = reinterpret_cast<const ull*>(&S[LS + (ig + 12) * 132]) + eh * 16;
    const ull* Cp = reinterpret_cast<const ull*>(&S[CS]) + eh * 16;
    float* Eq = &S[ES + eh * 4160];

    for (int jt = 0; jt < 4; jt++) {
        __syncthreads();
        const float* Rg = g_R + (b * 256 + jt * 64) * 128;
#pragma unroll
        for (int t = 0; t < 8; t++) {
            int idx = t * 256 + tid;      // 2048 float4
            int row = idx >> 5, c4 = idx & 31;
            float4 v = *reinterpret_cast<const float4*>(Rg + row * 128 + c4 * 4);
            float* d = &S[RS + row * 130 + c4 * 4];
            *reinterpret_cast<float2*>(d) = make_float2(v.x, v.y);
            *reinterpret_cast<float2*>(d + 2) = make_float2(v.z, v.w);
        }
        __syncthreads();

        const ull* Rp0 = reinterpret_cast<const ull*>(&S[RS + (jg) * 130]) + eh * 16;
        const ull* Rp1 = reinterpret_cast<const ull*>(&S[RS + (jg + 16) * 130]) + eh * 16;
        const ull* Rp2 = reinterpret_cast<const ull*>(&S[RS + (jg + 32) * 130]) + eh * 16;
        const ull* Rp3 = reinterpret_cast<const ull*>(&S[RS + (jg + 48) * 130]) + eh * 16;

        ull acc[4][4];
#pragma unroll
        for (int u = 0; u < 4; u++)
#pragma unroll
            for (int v = 0; v < 4; v++) acc[u][v] = 0ULL;

#pragma unroll 4
        for (int ep = 0; ep < 16; ep++) {
            ull c = Cp[ep];
            ull l0 = Lp0[ep], l1 = Lp1[ep], l2 = Lp2[ep], l3 = Lp3[ep];
            ull r0 = Rp0[ep], r1 = Rp1[ep], r2 = Rp2[ep], r3 = Rp3[ep];
            acc[0][0] = f2_fma(f2_add(l0, r0) & ABSM, c, acc[0][0]);
            acc[0][1] = f2_fma(f2_add(l0, r1) & ABSM, c, acc[0][1]);
            acc[0][2] = f2_fma(f2_add(l0, r2) & ABSM, c, acc[0][2]);
            acc[0][3] = f2_fma(f2_add(l0, r3) & ABSM, c, acc[0][3]);
            acc[1][0] = f2_fma(f2_add(l1, r0) & ABSM, c, acc[1][0]);
            acc[1][1] = f2_fma(f2_add(l1, r1) & ABSM, c, acc[1][1]);
            acc[1][2] = f2_fma(f2_add(l1, r2) & ABSM, c, acc[1][2]);
            acc[1][3] = f2_fma(f2_add(l1, r3) & ABSM, c, acc[1][3]);
            acc[2][0] = f2_fma(f2_add(l2, r0) & ABSM, c, acc[2][0]);
            acc[2][1] = f2_fma(f2_add(l2, r1) & ABSM, c, acc[2][1]);
            acc[2][2] = f2_fma(f2_add(l2, r2) & ABSM, c, acc[2][2]);
            acc[2][3] = f2_fma(f2_add(l2, r3) & ABSM, c, acc[2][3]);
            acc[3][0] = f2_fma(f2_add(l3, r0) & ABSM, c, acc[3][0]);
            acc[3][1] = f2_fma(f2_add(l3, r1) & ABSM, c, acc[3][1]);
            acc[3][2] = f2_fma(f2_add(l3, r2) & ABSM, c, acc[3][2]);
            acc[3][3] = f2_fma(f2_add(l3, r3) & ABSM, c, acc[3][3]);
        }
#pragma unroll
        for (int u = 0; u < 4; u++) {
            int i = ig + 4 * u;
#pragma unroll
            for (int v = 0; v < 4; v++) {
                int j = jt * 64 + jg + 16 * v;
                Eq[i * 260 + j] = f2_hadd(acc[u][v]);
            }
        }
    }
    __syncthreads();

    // softmax over j: 8 warps x 2 rows; combine 4 e-quarters + linear terms here
    int wid = tid >> 5, lane = tid & 31;
#pragma unroll
    for (int s = 0; s < 2; s++) {
        int rr = wid * 2 + s;
        float sl = S[SLS + rr];
        const float* bp = bias_kk + (i0 + rr) * 256;
        float v[8];
        float m = -1e30f;
#pragma unroll
        for (int u = 0; u < 8; u++) {
            int c = u * 32 + lane;
            int o = rr * 260 + c;
            v[u] = S[ES + o] + S[ES + 4160 + o] + S[ES + 8320 + o] + S[ES + 12480 + o]
                 + sl + S[SRS + c] + bp[c];
            m = fmaxf(m, v[u]);
        }
#pragma unroll
        for (int o = 16; o > 0; o >>= 1) m = fmaxf(m, __shfl_xor_sync(0xffffffffu, m, o));
        float sum = 0.f;
#pragma unroll
        for (int u = 0; u < 8; u++) {
            float p = __expf(v[u] - m);
            S[ES + rr * 260 + u * 32 + lane] = p;
            sum += p;
        }
#pragma unroll
        for (int o = 16; o > 0; o >>= 1) sum += __shfl_xor_sync(0xffffffffu, sum, o);
        if (lane == 0) S[INVS + rr] = 1.f / sum;
    }
    __syncthreads();

    // h: thread = (w in 64, q = j-half, ih = i-half of 8); f[8] accumulators
    int w = tid & 63;
    int q = (tid >> 6) & 1;
    int ih = tid >> 7;
    ull f[8];
#pragma unroll
    for (int ii = 0; ii < 8; ii++) f[ii] = 0ULL;
    const float* xp = x + b * 16384 + w * 256 + q * 128;
    const float* pbase = &S[ES + (ih * 8) * 260 + q * 128];
    for (int j4 = 0; j4 < 32; j4++) {
        ulonglong2 xq = *reinterpret_cast<const ulonglong2*>(xp + j4 * 4);
#pragma unroll
        for (int ii = 0; ii < 8; ii++) {
            ulonglong2 pq = *reinterpret_cast<const ulonglong2*>(pbase + ii * 260 + j4 * 4);
            f[ii] = f2_fma(xq.x, pq.x, f[ii]);
            f[ii] = f2_fma(xq.y, pq.y, f[ii]);
        }
    }
#pragma unroll
    for (int ii = 0; ii < 8; ii++)
        S[RS + q * 1024 + (ih * 8 + ii) * 64 + w] = f2_hadd(f[ii]);
    __syncthreads();

#pragma unroll
    for (int t = 0; t < 4; t++) {
        int idx = t * 256 + tid;
        int ii = idx >> 6, w2 = idx & 63;
        float sum = S[RS + ii * 64 + w2] + S[RS + 1024 + ii * 64 + w2];
        float val = sum * S[INVS + ii];
        g_h[(b * 256 + i0 + ii) * 64 + w2] = 1.f / (1.f + __expf(-val));
    }
}

// ---------------------------------------------------------------------------
// k3: out[b,w,o] = sum_k h[b,k,w] fc_w[o,k] + fc_b[o]
// grid = 128 (16b x 8 wtiles of 8), 256 thr, single staging + 1 sync
// dynamic smem 74,304 B
// ---------------------------------------------------------------------------
__global__ void __launch_bounds__(256, 2)
k3_fc(const float* __restrict__ fc_w, const float* __restrict__ fc_b,
      float* __restrict__ out) {
    extern __shared__ float T[];
    const int FW = 0;       // 64 x 258
    const int HS = 16512;   // 8 x 258

    int bx = blockIdx.x;
    int b = bx >> 3, wq = bx & 7;
    int w0 = wq * 8;
    int tid = threadIdx.x;
    int w8 = tid & 7, og = tid >> 3;

#pragma unroll
    for (int t = 0; t < 16; t++) {
        int idx = t * 256 + tid;          // 4096 float4
        int row = idx >> 6, c4 = idx & 63;
        float4 v = *reinterpret_cast<const float4*>(fc_w + row * 256 + c4 * 4);
        float* d = &T[FW + row * 258 + c4 * 4];
        *reinterpret_cast<float2*>(d) = make_float2(v.x, v.y);
        *reinterpret_cast<float2*>(d + 2) = make_float2(v.z, v.w);
    }
#pragma unroll
    for (int t = 0; t < 8; t++) {
        int idx = t * 256 + tid;          // 2048 scalars
        int kk = idx >> 3, ww = idx & 7;
        T[HS + ww * 258 + kk] = g_h[(b * 256 + kk) * 64 + w0 + ww];
    }
    __syncthreads();

    const ull* hp = reinterpret_cast<const ull*>(&T[HS + w8 * 258]);
    const ull* f0 = reinterpret_cast<const ull*>(&T[FW + og * 258]);
    const ull* f1 = reinterpret_cast<const ull*>(&T[FW + (og + 32) * 258]);
    ull acc0 = 0ULL, acc1 = 0ULL;
#pragma unroll 16
    for (int kp = 0; kp < 128; kp++) {
        ull h2 = hp[kp];
        acc0 = f2_fma(h2, f0[kp], acc0);
        acc1 = f2_fma(h2, f1[kp], acc1);
    }
    out[(b * 64 + w0 + w8) * 64 + og] = f2_hadd(acc0) + fc_b[og];
    out[(b * 64 + w0 + w8) * 64 + og + 32] = f2_hadd(acc1) + fc_b[og + 32];
}

// ---------------------------------------------------------------------------
extern "C" void kernel_launch(void* const* d_in, const int* in_sizes, int n_in,
                              void* d_out, int out_size) {
    const float* x       = (const float*)d_in[0];
    const float* lin_w   = (const float*)d_in[1];
    const float* lin_b   = (const float*)d_in[2];
    const float* a       = (const float*)d_in[3];
    const float* bias_kk = (const float*)d_in[4];
    const float* fc_w    = (const float*)d_in[5];
    const float* fc_b    = (const float*)d_in[6];
    float* out = (float*)d_out;

    cudaFuncSetAttribute(k2_attn, cudaFuncAttributeMaxDynamicSharedMemorySize, 109952);
    cudaFuncSetAttribute(k3_fc, cudaFuncAttributeMaxDynamicSharedMemorySize, 74304);

    k1_lr<<<256, 128>>>(x, lin_w, lin_b);
    k1b_s<<<256, 128>>>(a);
    k2_attn<<<256, 256, 109952>>>(x, bias_kk, a);
    k3_fc<<<128, 256, 74304>>>(fc_w, fc_b, out);
}

// round 6
// speedup vs baseline: 1.0907x; 1.0907x over previous
#include <cuda_runtime.h>

// B=16, Wn=64, K=256, E=128, O=64

typedef unsigned long long ull;

__device__ __forceinline__ ull f2_add(ull a, ull b) {
    ull r; asm("add.rn.f32x2 %0,%1,%2;" : "=l"(r) : "l"(a), "l"(b)); return r;
}
__device__ __forceinline__ ull f2_fma(ull a, ull b, ull c) {
    ull r; asm("fma.rn.f32x2 %0,%1,%2,%3;" : "=l"(r) : "l"(a), "l"(b), "l"(c)); return r;
}
__device__ __forceinline__ float f2_hadd(ull a) {
    float lo, hi; asm("mov.b64 {%0,%1},%2;" : "=f"(lo), "=f"(hi) : "l"(a)); return lo + hi;
}
__device__ __forceinline__ ull f2_dup(float v) {
    ull r; asm("mov.b64 %0,{%1,%1};" : "=l"(r) : "f"(v)); return r;
}
__device__ __forceinline__ void f2_unpack(ull a, float& lo, float& hi) {
    asm("mov.b64 {%0,%1},%2;" : "=f"(lo), "=f"(hi) : "l"(a));
}

// Scratch
__device__ float g_L[16 * 256 * 128];
__device__ float g_R[16 * 256 * 128];
__device__ float g_sL[16 * 256];
__device__ float g_sR[16 * 256];
__device__ float g_h[16 * 256 * 64];

// ---------------------------------------------------------------------------
// k1: C[4096,256] = A[4096,64] x W[256,64]^T ; 8m x 4n register tiles.
// Fused: sL/sR row-dot partials reduced via shfl + atomic add (REDG).
// grid = 256 blocks, 128 threads
// ---------------------------------------------------------------------------
__global__ void __launch_bounds__(128, 4)
k1_lr(const float* __restrict__ x, const float* __restrict__ lin_w,
      const float* __restrict__ lin_b, const float* __restrict__ a) {
    __shared__ float As[64 * 68];
    __shared__ float Ws[64 * 68];

    int bx = blockIdx.x;
    int mt = bx >> 2, nt = bx & 3;
    int b = mt >> 2, k0 = (mt & 3) * 64;
    int half = nt >> 1, e0 = (nt & 1) * 64;
    int tid = threadIdx.x;

#pragma unroll
    for (int t = 0; t < 8; t++) {
        int idx = t * 128 + tid;
        int w = idx >> 4, m4 = idx & 15;
        float4 v = *reinterpret_cast<const float4*>(x + b * 16384 + w * 256 + k0 + m4 * 4);
        *reinterpret_cast<float4*>(&As[w * 68 + m4 * 4]) = v;
    }
#pragma unroll
    for (int t = 0; t < 8; t++) {
        int idx = t * 128 + tid;
        int n = idx >> 4, w4 = idx & 15;
        float4 v = *reinterpret_cast<const float4*>(lin_w + (e0 + n) * 128 + half * 64 + w4 * 4);
        Ws[(w4 * 4 + 0) * 68 + n] = v.x;
        Ws[(w4 * 4 + 1) * 68 + n] = v.y;
        Ws[(w4 * 4 + 2) * 68 + n] = v.z;
        Ws[(w4 * 4 + 3) * 68 + n] = v.w;
    }
    __syncthreads();

    int mg = tid >> 4, ng = tid & 15;
    ull acc[4][4];
#pragma unroll
    for (int n = 0; n < 4; n++)
#pragma unroll
        for (int p = 0; p < 4; p++) acc[n][p] = 0ULL;

#pragma unroll 8
    for (int w = 0; w < 64; w++) {
        const ull* ap = reinterpret_cast<const ull*>(&As[w * 68 + mg * 8]);
        ull a0 = ap[0], a1 = ap[1], a2 = ap[2], a3 = ap[3];
        float4 wn = *reinterpret_cast<const float4*>(&Ws[w * 68 + ng * 4]);
        ull w0 = f2_dup(wn.x), w1 = f2_dup(wn.y), w2 = f2_dup(wn.z), w3 = f2_dup(wn.w);
        acc[0][0] = f2_fma(a0, w0, acc[0][0]); acc[0][1] = f2_fma(a1, w0, acc[0][1]);
        acc[0][2] = f2_fma(a2, w0, acc[0][2]); acc[0][3] = f2_fma(a3, w0, acc[0][3]);
        acc[1][0] = f2_fma(a0, w1, acc[1][0]); acc[1][1] = f2_fma(a1, w1, acc[1][1]);
        acc[1][2] = f2_fma(a2, w1, acc[1][2]); acc[1][3] = f2_fma(a3, w1, acc[1][3]);
        acc[2][0] = f2_fma(a0, w2, acc[2][0]); acc[2][1] = f2_fma(a1, w2, acc[2][1]);
        acc[2][2] = f2_fma(a2, w2, acc[2][2]); acc[2][3] = f2_fma(a3, w2, acc[2][3]);
        acc[3][0] = f2_fma(a0, w3, acc[3][0]); acc[3][1] = f2_fma(a1, w3, acc[3][1]);
        acc[3][2] = f2_fma(a2, w3, acc[3][2]); acc[3][3] = f2_fma(a3, w3, acc[3][3]);
    }

    float4 lb4 = make_float4(0.f, 0.f, 0.f, 0.f);
    if (half == 0) lb4 = *reinterpret_cast<const float4*>(lin_b + e0 + ng * 4);
    float4 a6 = *reinterpret_cast<const float4*>(a + e0 + ng * 4);
    a6.x *= 0.6f; a6.y *= 0.6f; a6.z *= 0.6f; a6.w *= 0.6f;

    float* outbase = (half ? g_R : g_L) + (b * 256 + k0 + mg * 8) * 128 + e0 + ng * 4;
    float part[8];
#pragma unroll
    for (int p = 0; p < 4; p++) {
        float lo[4], hi[4];
#pragma unroll
        for (int n = 0; n < 4; n++) f2_unpack(acc[n][p], lo[n], hi[n]);
        float l0 = lo[0] + lb4.x, l1 = lo[1] + lb4.y, l2 = lo[2] + lb4.z, l3 = lo[3] + lb4.w;
        float h0 = hi[0] + lb4.x, h1 = hi[1] + lb4.y, h2 = hi[2] + lb4.z, h3 = hi[3] + lb4.w;
        *reinterpret_cast<float4*>(outbase + (2 * p) * 128) = make_float4(l0, l1, l2, l3);
        *reinterpret_cast<float4*>(outbase + (2 * p + 1) * 128) = make_float4(h0, h1, h2, h3);
        part[2 * p]     = l0 * a6.x + l1 * a6.y + l2 * a6.z + l3 * a6.w;
        part[2 * p + 1] = h0 * a6.x + h1 * a6.y + h2 * a6.z + h3 * a6.w;
    }
    // reduce over ng (16 lanes within half-warp)
#pragma unroll
    for (int o = 8; o > 0; o >>= 1) {
#pragma unroll
        for (int r = 0; r < 8; r++)
            part[r] += __shfl_down_sync(0xffffffffu, part[r], o, 16);
    }
    if (ng == 0) {
        float* sp = (half ? g_sR : g_sL) + b * 256 + k0 + mg * 8;
#pragma unroll
        for (int r = 0; r < 8; r++) atomicAdd(sp + r, part[r]);
    }
}

// ---------------------------------------------------------------------------
// k2: e-scores + softmax + h.  grid = 128 (16b x 8 itiles of 32), 256 thr.
// e-phase: 128 (ig x jg) slots x 2 e-halves; 4i x 4j tiles; R tiles prefetched
// into registers (double-buffered). smem 118,528 B.
// ---------------------------------------------------------------------------
__global__ void __launch_bounds__(256, 1)
k2_attn(const float* __restrict__ x, const float* __restrict__ bias_kk,
        const float* __restrict__ a) {
    extern __shared__ float S[];
    const int LS = 0;        // 32 x 132
    const int RS = 4224;     // 64 x 130  (reused as h partials 2x32x64)
    const int ES = 12544;    // 32 x 260  eh=0 partials -> probabilities
    const int ES2 = 20864;   // 32 x 260  eh=1 partials
    const int CS = 29184;    // 128
    const int SRS = 29312;   // 256
    const int SLS = 29568;   // 32
    const int INVS = 29600;  // 32
    const ull ABSM = 0x7FFFFFFF7FFFFFFFULL;

    int tid = threadIdx.x;
    int b = blockIdx.x >> 3;
    int i0 = (blockIdx.x & 7) << 5;

    const float* Lg = g_L + (b * 256 + i0) * 128;
#pragma unroll
    for (int t = 0; t < 4; t++) {
        int idx = t * 256 + tid;
        int row = idx >> 5, c4 = idx & 31;
        float4 v = *reinterpret_cast<const float4*>(Lg + row * 128 + c4 * 4);
        *reinterpret_cast<float4*>(&S[LS + row * 132 + c4 * 4]) = v;
    }
    if (tid < 128) S[CS + tid] = 0.4f * a[tid];
    S[SRS + tid] = g_sR[b * 256 + tid];
    if (tid < 32) S[SLS + tid] = g_sL[b * 256 + i0 + tid];

    int eh = tid >> 7;
    int r = tid & 127;
    int ig = r >> 4;
    int jg = r & 15;
    const ull* Lp0 = reinterpret_cast<const ull*>(&S[LS + (ig) * 132]) + eh * 32;
    const ull* Lp1 = reinterpret_cast<const ull*>(&S[LS + (ig + 8) * 132]) + eh * 32;
    const ull* Lp2 = reinterpret_cast<const ull*>(&S[LS + (ig + 16) * 132]) + eh * 32;
    const ull* Lp3 = reinterpret_cast<const ull*>(&S[LS + (ig + 24) * 132]) + eh * 32;
    const ull* Cp = reinterpret_cast<const ull*>(&S[CS]) + eh * 32;
    float* Eq = eh ? &S[ES2] : &S[ES];

    // prefetch R(jt=0) into registers
    const float* Rg0 = g_R + (b * 256) * 128;
    int st_row = tid >> 2, st_c4 = tid & 3;   // each thread: 8 c4 slots in one... (see loop)
    float4 pf[8];
#pragma unroll
    for (int t = 0; t < 8; t++) {
        int idx = t * 256 + tid;
        int row = idx >> 5, c4 = idx & 31;
        pf[t] = *reinterpret_cast<const float4*>(Rg0 + row * 128 + c4 * 4);
    }
    (void)st_row; (void)st_c4;

    for (int jt = 0; jt < 4; jt++) {
        __syncthreads();   // previous compute done reading RS
#pragma unroll
        for (int t = 0; t < 8; t++) {
            int idx = t * 256 + tid;
            int row = idx >> 5, c4 = idx & 31;
            float* d = &S[RS + row * 130 + c4 * 4];
            *reinterpret_cast<float2*>(d) = make_float2(pf[t].x, pf[t].y);
            *reinterpret_cast<float2*>(d + 2) = make_float2(pf[t].z, pf[t].w);
        }
        __syncthreads();   // RS ready

        if (jt < 3) {      // prefetch next stage; latency hidden under compute
            const float* Rgn = g_R + (b * 256 + (jt + 1) * 64) * 128;
#pragma unroll
            for (int t = 0; t < 8; t++) {
                int idx = t * 256 + tid;
                int row = idx >> 5, c4 = idx & 31;
                pf[t] = *reinterpret_cast<const float4*>(Rgn + row * 128 + c4 * 4);
            }
        }

        const ull* Rp0 = reinterpret_cast<const ull*>(&S[RS + (jg) * 130]) + eh * 32;
        const ull* Rp1 = reinterpret_cast<const ull*>(&S[RS + (jg + 16) * 130]) + eh * 32;
        const ull* Rp2 = reinterpret_cast<const ull*>(&S[RS + (jg + 32) * 130]) + eh * 32;
        const ull* Rp3 = reinterpret_cast<const ull*>(&S[RS + (jg + 48) * 130]) + eh * 32;

        ull acc[4][4];
#pragma unroll
        for (int u = 0; u < 4; u++)
#pragma unroll
            for (int v = 0; v < 4; v++) acc[u][v] = 0ULL;

#pragma unroll 4
        for (int ep = 0; ep < 32; ep++) {
            ull c = Cp[ep];
            ull l0 = Lp0[ep], l1 = Lp1[ep], l2 = Lp2[ep], l3 = Lp3[ep];
            ull r0 = Rp0[ep], r1 = Rp1[ep], r2 = Rp2[ep], r3 = Rp3[ep];
            acc[0][0] = f2_fma(f2_add(l0, r0) & ABSM, c, acc[0][0]);
            acc[0][1] = f2_fma(f2_add(l0, r1) & ABSM, c, acc[0][1]);
            acc[0][2] = f2_fma(f2_add(l0, r2) & ABSM, c, acc[0][2]);
            acc[0][3] = f2_fma(f2_add(l0, r3) & ABSM, c, acc[0][3]);
            acc[1][0] = f2_fma(f2_add(l1, r0) & ABSM, c, acc[1][0]);
            acc[1][1] = f2_fma(f2_add(l1, r1) & ABSM, c, acc[1][1]);
            acc[1][2] = f2_fma(f2_add(l1, r2) & ABSM, c, acc[1][2]);
            acc[1][3] = f2_fma(f2_add(l1, r3) & ABSM, c, acc[1][3]);
            acc[2][0] = f2_fma(f2_add(l2, r0) & ABSM, c, acc[2][0]);
            acc[2][1] = f2_fma(f2_add(l2, r1) & ABSM, c, acc[2][1]);
            acc[2][2] = f2_fma(f2_add(l2, r2) & ABSM, c, acc[2][2]);
            acc[2][3] = f2_fma(f2_add(l2, r3) & ABSM, c, acc[2][3]);
            acc[3][0] = f2_fma(f2_add(l3, r0) & ABSM, c, acc[3][0]);
            acc[3][1] = f2_fma(f2_add(l3, r1) & ABSM, c, acc[3][1]);
            acc[3][2] = f2_fma(f2_add(l3, r2) & ABSM, c, acc[3][2]);
            acc[3][3] = f2_fma(f2_add(l3, r3) & ABSM, c, acc[3][3]);
        }
#pragma unroll
        for (int u = 0; u < 4; u++) {
            int i = ig + 8 * u;
#pragma unroll
            for (int v = 0; v < 4; v++) {
                int j = jt * 64 + jg + 16 * v;
                Eq[i * 260 + j] = f2_hadd(acc[u][v]);
            }
        }
    }
    __syncthreads();

    // softmax over j: 8 warps x 4 rows; fold e-halves + linear terms here
    int wid = tid >> 5, lane = tid & 31;
#pragma unroll
    for (int s = 0; s < 4; s++) {
        int rr = wid * 4 + s;
        float sl = S[SLS + rr];
        const float* bp = bias_kk + (i0 + rr) * 256;
        float v[8];
        float m = -1e30f;
#pragma unroll
        for (int u = 0; u < 8; u++) {
            int c = u * 32 + lane;
            int o = rr * 260 + c;
            v[u] = S[ES + o] + S[ES2 + o] + sl + S[SRS + c] + bp[c];
            m = fmaxf(m, v[u]);
        }
#pragma unroll
        for (int o = 16; o > 0; o >>= 1) m = fmaxf(m, __shfl_xor_sync(0xffffffffu, m, o));
        float sum = 0.f;
#pragma unroll
        for (int u = 0; u < 8; u++) {
            float p = __expf(v[u] - m);
            S[ES + rr * 260 + u * 32 + lane] = p;
            sum += p;
        }
#pragma unroll
        for (int o = 16; o > 0; o >>= 1) sum += __shfl_xor_sync(0xffffffffu, sum, o);
        if (lane == 0) S[INVS + rr] = 1.f / sum;
    }
    __syncthreads();

    // h: thread = (w in 64, q = j-half, ih = i-half); f[16]
    int w = tid & 63;
    int q = (tid >> 6) & 1;
    int ih = tid >> 7;
    ull f[16];
#pragma unroll
    for (int ii = 0; ii < 16; ii++) f[ii] = 0ULL;
    const float* xp = x + b * 16384 + w * 256 + q * 128;
    const float* pbase = &S[ES + (ih * 16) * 260 + q * 128];
    for (int j4 = 0; j4 < 32; j4++) {
        ulonglong2 xq = *reinterpret_cast<const ulonglong2*>(xp + j4 * 4);
#pragma unroll
        for (int ii = 0; ii < 16; ii++) {
            ulonglong2 pq = *reinterpret_cast<const ulonglong2*>(pbase + ii * 260 + j4 * 4);
            f[ii] = f2_fma(xq.x, pq.x, f[ii]);
            f[ii] = f2_fma(xq.y, pq.y, f[ii]);
        }
    }
#pragma unroll
    for (int ii = 0; ii < 16; ii++)
        S[RS + q * 2048 + (ih * 16 + ii) * 64 + w] = f2_hadd(f[ii]);
    __syncthreads();

#pragma unroll
    for (int t = 0; t < 8; t++) {
        int idx = t * 256 + tid;
        int ii = idx >> 6, w2 = idx & 63;
        float sum = S[RS + ii * 64 + w2] + S[RS + 2048 + ii * 64 + w2];
        float val = sum * S[INVS + ii];
        g_h[(b * 256 + i0 + ii) * 64 + w2] = 1.f / (1.f + __expf(-val));
    }
}

// ---------------------------------------------------------------------------
// k3: out[b,w,o] = sum_k h[b,k,w] fc_w[o,k] + fc_b[o]
// grid = 128 (16b x 8 wtiles of 8), 256 thr, single staging + 1 sync
// ---------------------------------------------------------------------------
__global__ void __launch_bounds__(256, 2)
k3_fc(const float* __restrict__ fc_w, const float* __restrict__ fc_b,
      float* __restrict__ out) {
    extern __shared__ float T[];
    const int FW = 0;       // 64 x 258
    const int HS = 16512;   // 8 x 258

    int bx = blockIdx.x;
    int b = bx >> 3, wq = bx & 7;
    int w0 = wq * 8;
    int tid = threadIdx.x;
    int w8 = tid & 7, og = tid >> 3;

#pragma unroll
    for (int t = 0; t < 16; t++) {
        int idx = t * 256 + tid;
        int row = idx >> 6, c4 = idx & 63;
        float4 v = *reinterpret_cast<const float4*>(fc_w + row * 256 + c4 * 4);
        float* d = &T[FW + row * 258 + c4 * 4];
        *reinterpret_cast<float2*>(d) = make_float2(v.x, v.y);
        *reinterpret_cast<float2*>(d + 2) = make_float2(v.z, v.w);
    }
#pragma unroll
    for (int t = 0; t < 8; t++) {
        int idx = t * 256 + tid;
        int kk = idx >> 3, ww = idx & 7;
        T[HS + ww * 258 + kk] = g_h[(b * 256 + kk) * 64 + w0 + ww];
    }
    __syncthreads();

    const ull* hp = reinterpret_cast<const ull*>(&T[HS + w8 * 258]);
    const ull* f0 = reinterpret_cast<const ull*>(&T[FW + og * 258]);
    const ull* f1 = reinterpret_cast<const ull*>(&T[FW + (og + 32) * 258]);
    ull acc0 = 0ULL, acc1 = 0ULL;
#pragma unroll 16
    for (int kp = 0; kp < 128; kp++) {
        ull h2 = hp[kp];
        acc0 = f2_fma(h2, f0[kp], acc0);
        acc1 = f2_fma(h2, f1[kp], acc1);
    }
    out[(b * 64 + w0 + w8) * 64 + og] = f2_hadd(acc0) + fc_b[og];
    out[(b * 64 + w0 + w8) * 64 + og + 32] = f2_hadd(acc1) + fc_b[og + 32];
}

// ---------------------------------------------------------------------------
extern "C" void kernel_launch(void* const* d_in, const int* in_sizes, int n_in,
                              void* d_out, int out_size) {
    const float* x       = (const float*)d_in[0];
    const float* lin_w   = (const float*)d_in[1];
    const float* lin_b   = (const float*)d_in[2];
    const float* a       = (const float*)d_in[3];
    const float* bias_kk = (const float*)d_in[4];
    const float* fc_w    = (const float*)d_in[5];
    const float* fc_b    = (const float*)d_in[6];
    float* out = (float*)d_out;

    cudaFuncSetAttribute(k2_attn, cudaFuncAttributeMaxDynamicSharedMemorySize, 118528);
    cudaFuncSetAttribute(k3_fc, cudaFuncAttributeMaxDynamicSharedMemorySize, 74304);

    void* pL = nullptr; void* pR = nullptr;
    cudaGetSymbolAddress(&pL, g_sL);
    cudaGetSymbolAddress(&pR, g_sR);
    cudaMemsetAsync(pL, 0, 16 * 256 * sizeof(float));
    cudaMemsetAsync(pR, 0, 16 * 256 * sizeof(float));

    k1_lr<<<256, 128>>>(x, lin_w, lin_b, a);
    k2_attn<<<128, 256, 118528>>>(x, bias_kk, a);
    k3_fc<<<128, 256, 74304>>>(fc_w, fc_b, out);
}